// round 5
// baseline (speedup 1.0000x reference)
#include <cuda_runtime.h>

#define DIM 1024
#define M2  2048   // stacked [Re; Im] rows

// Ft[k][i] = F[i][k]  (k in [0,1024) = column of E, i in [0,2048) = Re/Im row)
__device__ float  g_F[DIM * M2];
__device__ float2 g_gate[2][10][4];
__device__ float  g_partials[128];

__device__ __forceinline__ float2 cmul(float2 a, float2 b) {
    return make_float2(a.x * b.x - a.y * b.y, a.x * b.y + a.y * b.x);
}
__device__ __forceinline__ float2 cadd(float2 a, float2 b) {
    return make_float2(a.x + b.x, a.y + b.y);
}

// ---------------------------------------------------------------------------
// Prep: fused per-qubit gate  G = RZ(tz) * RY(ty) * RX(tx)  for both signs.
// ---------------------------------------------------------------------------
__global__ void prep_kernel(const float* __restrict__ w) {
    int tid = threadIdx.x;
    if (tid >= 20) return;
    int s = tid / 10, q = tid % 10;
    float sign = s ? -1.f : 1.f;
    const float WM = 0.63245553203367586f;  // sqrt(2/5)
    float hx = 0.5f * sign * w[q]      * WM;
    float hy = 0.5f * sign * w[q + 10] * WM;
    float hz = 0.5f * sign * w[q + 20] * WM;
    float cx, sx, cy, sy, cz, sz;
    sincosf(hx, &sx, &cx);
    sincosf(hy, &sy, &cy);
    sincosf(hz, &sz, &cz);
    // T = RY * RX
    float2 T00 = make_float2( cy * cx,  sy * sx);
    float2 T01 = make_float2(-sy * cx, -cy * sx);
    float2 T10 = make_float2( sy * cx, -cy * sx);
    float2 T11 = make_float2( cy * cx, -sy * sx);
    float2 e0 = make_float2(cz, -sz);   // e^{-i tz/2}
    float2 e1 = make_float2(cz,  sz);   // e^{+i tz/2}
    g_gate[s][q][0] = cmul(e0, T00);
    g_gate[s][q][1] = cmul(e0, T01);
    g_gate[s][q][2] = cmul(e1, T10);
    g_gate[s][q][3] = cmul(e1, T11);
}

// ---------------------------------------------------------------------------
// Build F: one block simulates one basis column through the full circuit.
// Qubit q lives at bit position (9 - q).
// ---------------------------------------------------------------------------
__global__ __launch_bounds__(512) void build_kernel() {
    __shared__ float sr[DIM];
    __shared__ float si[DIM];
    int t   = threadIdx.x;
    int col = blockIdx.x;

    sr[t]        = (t == col)        ? 1.f : 0.f;  si[t]        = 0.f;
    sr[t + 512]  = (t + 512 == col)  ? 1.f : 0.f;  si[t + 512]  = 0.f;
    __syncthreads();

    for (int s = 0; s < 2; s++) {
        // 10 fused single-qubit rotations
        for (int q = 0; q < 10; q++) {
            int p = 9 - q;
            float2 g00 = g_gate[s][q][0], g01 = g_gate[s][q][1];
            float2 g10 = g_gate[s][q][2], g11 = g_gate[s][q][3];
            int lo = ((t >> p) << (p + 1)) | (t & ((1 << p) - 1));
            int hi = lo | (1 << p);
            float2 a0 = make_float2(sr[lo], si[lo]);
            float2 a1 = make_float2(sr[hi], si[hi]);
            float2 n0 = cadd(cmul(g00, a0), cmul(g01, a1));
            float2 n1 = cadd(cmul(g10, a0), cmul(g11, a1));
            sr[lo] = n0.x; si[lo] = n0.y;
            sr[hi] = n1.x; si[hi] = n1.y;
            __syncthreads();
        }
        // CNOT chain q=1..9 as one composite permutation gather:
        // psi_out[i] = psi[tau_1(tau_2(...tau_9(i)))],
        // tau_q(i): if control bit (10-q) set, flip target bit (9-q).
        int i0 = t, i1 = t + 512;
        int j0 = i0, j1 = i1;
        #pragma unroll
        for (int q = 9; q >= 1; q--) {
            int pc = 10 - q, pt = 9 - q;
            if ((j0 >> pc) & 1) j0 ^= (1 << pt);
            if ((j1 >> pc) & 1) j1 ^= (1 << pt);
        }
        float2 v0 = make_float2(sr[j0], si[j0]);
        float2 v1 = make_float2(sr[j1], si[j1]);
        __syncthreads();
        sr[i0] = v0.x; si[i0] = v0.y;
        sr[i1] = v1.x; si[i1] = v1.y;
        __syncthreads();
    }

    // Ft[col][i]: rows 0..1023 = Re, 1024..2047 = Im  (coalesced along i)
    g_F[col * M2 + t]              = sr[t];
    g_F[col * M2 + t + 512]        = sr[t + 512];
    g_F[col * M2 + 1024 + t]       = si[t];
    g_F[col * M2 + 1024 + t + 512] = si[t + 512];
}

// ---------------------------------------------------------------------------
// Fused GEMM + trace epilogue:
//   W = F @ x  (2048 x 1024 x 1024), partial = sum z'_i * F[i][j] * W[i][j]
// 128x128 block tile, BK=16, 256 threads, 8x8 per-thread microtile.
// ---------------------------------------------------------------------------
__global__ __launch_bounds__(256) void gemm_kernel(const float* __restrict__ x) {
    __shared__ float As[16][128];
    __shared__ float Bs[16][128];
    __shared__ float warpsum[8];

    int tid = threadIdx.x;
    int tx = tid & 15, ty = tid >> 4;
    int i0 = blockIdx.y * 128;   // M (row of F)
    int j0 = blockIdx.x * 128;   // N (col of x)

    float acc[8][8];
    #pragma unroll
    for (int m = 0; m < 8; m++)
        #pragma unroll
        for (int n = 0; n < 8; n++) acc[m][n] = 0.f;

    for (int k0 = 0; k0 < DIM; k0 += 16) {
        #pragma unroll
        for (int r = 0; r < 2; r++) {
            int v  = tid + r * 256;        // float4 slot in [0,512)
            int kk = v >> 5;
            int c4 = (v & 31) << 2;
            *(float4*)&As[kk][c4] = *(const float4*)&g_F[(k0 + kk) * M2  + i0 + c4];
            *(float4*)&Bs[kk][c4] = *(const float4*)&x  [(k0 + kk) * DIM + j0 + c4];
        }
        __syncthreads();
        #pragma unroll
        for (int kk = 0; kk < 16; kk++) {
            float a[8], b[8];
            *(float4*)&a[0] = *(float4*)&As[kk][ty * 8];
            *(float4*)&a[4] = *(float4*)&As[kk][ty * 8 + 4];
            *(float4*)&b[0] = *(float4*)&Bs[kk][tx * 8];
            *(float4*)&b[4] = *(float4*)&Bs[kk][tx * 8 + 4];
            #pragma unroll
            for (int m = 0; m < 8; m++)
                #pragma unroll
                for (int n = 0; n < 8; n++)
                    acc[m][n] = fmaf(a[m], b[n], acc[m][n]);
        }
        __syncthreads();
    }

    // Epilogue: part = sum_{m,n} z'(i) * F[i][j] * acc
    // F[i][j] = Ft[j*2048 + i]; vectorize along i (m) for 16B loads.
    float zs[8];
    #pragma unroll
    for (int m = 0; m < 8; m++) {
        int i = i0 + ty * 8 + m;
        zs[m] = (i & 16) ? -1.f : 1.f;
    }
    float part = 0.f;
    #pragma unroll
    for (int n = 0; n < 8; n++) {
        int j = j0 + tx * 8 + n;
        float4 f0 = *(const float4*)&g_F[j * M2 + i0 + ty * 8];
        float4 f1 = *(const float4*)&g_F[j * M2 + i0 + ty * 8 + 4];
        part += zs[0] * f0.x * acc[0][n] + zs[1] * f0.y * acc[1][n]
              + zs[2] * f0.z * acc[2][n] + zs[3] * f0.w * acc[3][n]
              + zs[4] * f1.x * acc[4][n] + zs[5] * f1.y * acc[5][n]
              + zs[6] * f1.z * acc[6][n] + zs[7] * f1.w * acc[7][n];
    }

    // Deterministic in-block reduction
    #pragma unroll
    for (int o = 16; o > 0; o >>= 1)
        part += __shfl_xor_sync(0xffffffffu, part, o);
    int w = tid >> 5, l = tid & 31;
    if (l == 0) warpsum[w] = part;
    __syncthreads();
    if (tid == 0) {
        float tot = 0.f;
        #pragma unroll
        for (int ww = 0; ww < 8; ww++) tot += warpsum[ww];
        g_partials[blockIdx.y * gridDim.x + blockIdx.x] = tot;
    }
}

__global__ void reduce_kernel(float* __restrict__ out) {
    __shared__ float s[128];
    int t = threadIdx.x;
    s[t] = g_partials[t];
    __syncthreads();
    for (int st = 64; st > 0; st >>= 1) {
        if (t < st) s[t] += s[t + st];
        __syncthreads();
    }
    if (t == 0) out[0] = s[0];
}

extern "C" void kernel_launch(void* const* d_in, const int* in_sizes, int n_in,
                              void* d_out, int out_size) {
    const float* x = (const float*)d_in[0];      // 1024x1024 row-major
    const float* w = (const float*)d_in[1];      // 30 weights
    prep_kernel<<<1, 32>>>(w);
    build_kernel<<<DIM, 512>>>();
    gemm_kernel<<<dim3(8, 16), 256>>>(x);
    reduce_kernel<<<1, 128>>>((float*)d_out);
}

// round 7
// speedup vs baseline: 1.9282x; 1.9282x over previous
#include <cuda_runtime.h>
#include <cuda_bf16.h>
#include <cstdint>

#define DIM 1024
#define M2  2048   // stacked [Re; Im] rows

// Ft[k][i] = F[i][k]  (epilogue reads this, coalesced along i)
__device__ float         g_F  [DIM * M2];
// GEMM operands, K-major: A[i][k] (2048x1024), B[j][k] = x^T splits (1024x1024)
__device__ __nv_bfloat16 g_Ahi[M2 * DIM];
__device__ __nv_bfloat16 g_Alo[M2 * DIM];
__device__ __nv_bfloat16 g_Bhi[DIM * DIM];
__device__ __nv_bfloat16 g_Blo[DIM * DIM];
__device__ float         g_partials[128];

__device__ __forceinline__ uint32_t smem_to_u32(const void* p) {
    uint32_t a;
    asm("{ .reg .u64 t; cvta.to.shared.u64 t, %1; cvt.u32.u64 %0, t; }" : "=r"(a) : "l"(p));
    return a;
}

#define CP_ASYNC16(dst, src) \
    asm volatile("cp.async.ca.shared.global [%0], [%1], 16;" :: "r"(dst), "l"(src) : "memory")
#define CP_COMMIT() asm volatile("cp.async.commit_group;" ::: "memory")
#define CP_WAIT1()  asm volatile("cp.async.wait_group 1;" ::: "memory")
#define CP_WAIT0()  asm volatile("cp.async.wait_group 0;" ::: "memory")

#define LDSM_X4(r, a) \
    asm volatile("ldmatrix.sync.aligned.m8n8.x4.shared.b16 {%0,%1,%2,%3}, [%4];" \
        : "=r"((r)[0]), "=r"((r)[1]), "=r"((r)[2]), "=r"((r)[3]) : "r"(a))

#define MMA_BF16(d, a, b) \
    asm volatile("mma.sync.aligned.m16n8k16.row.col.f32.bf16.bf16.f32 " \
        "{%0,%1,%2,%3},{%4,%5,%6,%7},{%8,%9},{%0,%1,%2,%3};" \
        : "+f"((d)[0]), "+f"((d)[1]), "+f"((d)[2]), "+f"((d)[3]) \
        : "r"((a)[0]), "r"((a)[1]), "r"((a)[2]), "r"((a)[3]), \
          "r"((b)[0]), "r"((b)[1]))

__device__ __forceinline__ float2 cmul(float2 a, float2 b) {
    return make_float2(a.x * b.x - a.y * b.y, a.x * b.y + a.y * b.x);
}
__device__ __forceinline__ float2 cadd(float2 a, float2 b) {
    return make_float2(a.x + b.x, a.y + b.y);
}

// ---------------------------------------------------------------------------
// Build F (gate prep fused in): one block per basis column.
// ---------------------------------------------------------------------------
__global__ __launch_bounds__(512) void build_kernel(const float* __restrict__ w) {
    __shared__ float  sr[DIM];
    __shared__ float  si[DIM];
    __shared__ float2 sg[2][10][4];
    int t   = threadIdx.x;
    int col = blockIdx.x;

    if (t < 20) {
        int s = t / 10, q = t % 10;
        float sign = s ? -1.f : 1.f;
        const float WM = 0.63245553203367586f;  // sqrt(2/5)
        float hx = 0.5f * sign * w[q]      * WM;
        float hy = 0.5f * sign * w[q + 10] * WM;
        float hz = 0.5f * sign * w[q + 20] * WM;
        float cx, sx, cy, sy, cz, sz;
        sincosf(hx, &sx, &cx);
        sincosf(hy, &sy, &cy);
        sincosf(hz, &sz, &cz);
        float2 T00 = make_float2( cy * cx,  sy * sx);
        float2 T01 = make_float2(-sy * cx, -cy * sx);
        float2 T10 = make_float2( sy * cx, -cy * sx);
        float2 T11 = make_float2( cy * cx, -sy * sx);
        float2 e0 = make_float2(cz, -sz);
        float2 e1 = make_float2(cz,  sz);
        sg[s][q][0] = cmul(e0, T00);
        sg[s][q][1] = cmul(e0, T01);
        sg[s][q][2] = cmul(e1, T10);
        sg[s][q][3] = cmul(e1, T11);
    }
    sr[t]       = (t == col)       ? 1.f : 0.f;  si[t]       = 0.f;
    sr[t + 512] = (t + 512 == col) ? 1.f : 0.f;  si[t + 512] = 0.f;
    __syncthreads();

    for (int s = 0; s < 2; s++) {
        for (int q = 0; q < 10; q++) {
            int p = 9 - q;
            float2 g00 = sg[s][q][0], g01 = sg[s][q][1];
            float2 g10 = sg[s][q][2], g11 = sg[s][q][3];
            int lo = ((t >> p) << (p + 1)) | (t & ((1 << p) - 1));
            int hi = lo | (1 << p);
            float2 a0 = make_float2(sr[lo], si[lo]);
            float2 a1 = make_float2(sr[hi], si[hi]);
            float2 n0 = cadd(cmul(g00, a0), cmul(g01, a1));
            float2 n1 = cadd(cmul(g10, a0), cmul(g11, a1));
            sr[lo] = n0.x; si[lo] = n0.y;
            sr[hi] = n1.x; si[hi] = n1.y;
            __syncthreads();
        }
        // CNOT chain q=1..9 as composite permutation gather
        int i0 = t, i1 = t + 512;
        int j0 = i0, j1 = i1;
        #pragma unroll
        for (int q = 9; q >= 1; q--) {
            int pc = 10 - q, pt = 9 - q;
            if ((j0 >> pc) & 1) j0 ^= (1 << pt);
            if ((j1 >> pc) & 1) j1 ^= (1 << pt);
        }
        float2 v0 = make_float2(sr[j0], si[j0]);
        float2 v1 = make_float2(sr[j1], si[j1]);
        __syncthreads();
        sr[i0] = v0.x; si[i0] = v0.y;
        sr[i1] = v1.x; si[i1] = v1.y;
        __syncthreads();
    }

    g_F[col * M2 + t]              = sr[t];
    g_F[col * M2 + t + 512]        = sr[t + 512];
    g_F[col * M2 + 1024 + t]       = si[t];
    g_F[col * M2 + 1024 + t + 512] = si[t + 512];
}

// ---------------------------------------------------------------------------
// Transpose + bf16 hi/lo split: z=0: g_F(Ft) -> A[i][k]; z=1: x -> B[j][k]=x^T
// ---------------------------------------------------------------------------
__global__ __launch_bounds__(256) void split_kernel(const float* __restrict__ x) {
    __shared__ float tile[32][33];
    int tx = threadIdx.x & 31, ty = threadIdx.x >> 5;
    int k0 = blockIdx.x * 32;
    int r0 = blockIdx.y * 32;

    if (blockIdx.z == 0) {
        #pragma unroll
        for (int r = 0; r < 4; r++)
            tile[ty + 8 * r][tx] = g_F[(k0 + ty + 8 * r) * M2 + r0 + tx];
        __syncthreads();
        #pragma unroll
        for (int r = 0; r < 4; r++) {
            float v = tile[tx][ty + 8 * r];
            __nv_bfloat16 h = __float2bfloat16(v);
            float lo = v - __bfloat162float(h);
            int idx = (r0 + ty + 8 * r) * DIM + k0 + tx;
            g_Ahi[idx] = h;
            g_Alo[idx] = __float2bfloat16(lo);
        }
    } else {
        if (r0 >= DIM) return;
        #pragma unroll
        for (int r = 0; r < 4; r++)
            tile[ty + 8 * r][tx] = x[(k0 + ty + 8 * r) * DIM + r0 + tx];
        __syncthreads();
        #pragma unroll
        for (int r = 0; r < 4; r++) {
            float v = tile[tx][ty + 8 * r];
            __nv_bfloat16 h = __float2bfloat16(v);
            float lo = v - __bfloat162float(h);
            int idx = (r0 + ty + 8 * r) * DIM + k0 + tx;
            g_Bhi[idx] = h;
            g_Blo[idx] = __float2bfloat16(lo);
        }
    }
}

// ---------------------------------------------------------------------------
// mma.sync split-bf16 GEMM + fused trace epilogue.
//   D = A @ B^T (2048x1024 x 1024x1024), D ~= AhBh + AhBl + AlBh (fp32 acc)
//   partial += z(i) * F[i][j] * D[i][j]
// CTA 128x128, 256 threads (8 warps, 2x4), warp tile 64x32, BK=32,
// cp.async double-buffered stages, 80B-padded rows for conflict-free ldmatrix.
// ---------------------------------------------------------------------------
#define ROWB    80                 // 64 data bytes (32 bf16) + 16 pad
#define TILE_B  (128 * ROWB)       // 10240
#define STAGE_B (4 * TILE_B)       // 40960
#define NSTAGE  32                 // K = 1024 / 32
#define GEMM_SMEM (2 * STAGE_B)    // 81920

__device__ __forceinline__ void issue_stage(uint32_t sb, int c, int tid, int i0, int j0) {
    uint32_t st = sb + (uint32_t)(c & 1) * STAGE_B;
    int k0 = c * 32;
    const __nv_bfloat16* bases[4] = { g_Ahi, g_Alo, g_Bhi, g_Blo };
    #pragma unroll
    for (int t4 = 0; t4 < 4; t4++) {
        const __nv_bfloat16* base = bases[t4];
        int r0 = (t4 < 2) ? i0 : j0;
        #pragma unroll
        for (int r = 0; r < 2; r++) {
            int slot = r * 256 + tid;
            int row = slot >> 2, seg = slot & 3;
            uint32_t dst = st + t4 * TILE_B + row * ROWB + seg * 16;
            const void* src = base + (size_t)(r0 + row) * DIM + k0 + seg * 8;
            CP_ASYNC16(dst, src);
        }
    }
    CP_COMMIT();
}

__global__ __launch_bounds__(256) void gemm_kernel() {
    extern __shared__ char smem[];
    __shared__ float ws[8];
    const uint32_t sb = smem_to_u32(smem);
    int tid = threadIdx.x;
    int w = tid >> 5, lane = tid & 31;
    int i0 = blockIdx.y * 128;
    int j0 = blockIdx.x * 128;
    int warpM = (w >> 2) * 64;
    int warpN = (w & 3) * 32;

    float acc[4][4][4];
    #pragma unroll
    for (int a = 0; a < 4; a++)
        #pragma unroll
        for (int b = 0; b < 4; b++)
            #pragma unroll
            for (int d = 0; d < 4; d++) acc[a][b][d] = 0.f;

    // ldmatrix lane addressing (fixed per thread)
    int arow = warpM + ((lane >> 3) & 1) * 8 + (lane & 7);
    int akb  = (lane >> 4) * 16;
    int brow = warpN + (lane >> 4) * 8 + (lane & 7);
    int bkb  = ((lane >> 3) & 1) * 16;

    issue_stage(sb, 0, tid, i0, j0);

    for (int c = 0; c < NSTAGE; c++) {
        if (c + 1 < NSTAGE) { issue_stage(sb, c + 1, tid, i0, j0); CP_WAIT1(); }
        else                { CP_WAIT0(); }
        __syncthreads();

        uint32_t st = sb + (uint32_t)(c & 1) * STAGE_B;
        #pragma unroll
        for (int ks = 0; ks < 2; ks++) {
            uint32_t ah[4][4], al[4][4], bh[4][2], bl[4][2];
            #pragma unroll
            for (int mt = 0; mt < 4; mt++) {
                uint32_t addr = st + (arow + mt * 16) * ROWB + ks * 32 + akb;
                LDSM_X4(ah[mt], addr);
                LDSM_X4(al[mt], addr + TILE_B);
            }
            #pragma unroll
            for (int np = 0; np < 2; np++) {
                uint32_t addr = st + 2 * TILE_B + (brow + np * 16) * ROWB + ks * 32 + bkb;
                uint32_t r[4];
                LDSM_X4(r, addr);
                bh[np * 2][0] = r[0]; bh[np * 2][1] = r[1];
                bh[np * 2 + 1][0] = r[2]; bh[np * 2 + 1][1] = r[3];
                LDSM_X4(r, addr + TILE_B);
                bl[np * 2][0] = r[0]; bl[np * 2][1] = r[1];
                bl[np * 2 + 1][0] = r[2]; bl[np * 2 + 1][1] = r[3];
            }
            #pragma unroll
            for (int mt = 0; mt < 4; mt++)
                #pragma unroll
                for (int nt = 0; nt < 4; nt++) {
                    MMA_BF16(acc[mt][nt], ah[mt], bh[nt]);
                    MMA_BF16(acc[mt][nt], ah[mt], bl[nt]);
                    MMA_BF16(acc[mt][nt], al[mt], bh[nt]);
                }
        }
        __syncthreads();
    }

    // Fused epilogue: part += z(i) * F[i][j] * D[i][j]
    // thread element map per m16n8 tile: (qr, qc2), (qr, qc2+1), (qr+8, qc2), (qr+8, qc2+1)
    int qr = lane >> 2, qc2 = (lane & 3) * 2;
    float part = 0.f;
    #pragma unroll
    for (int mt = 0; mt < 4; mt++) {
        int ib = i0 + warpM + mt * 16 + qr;
        float s0 = (ib & 16) ? -1.f : 1.f;
        float s1 = ((ib + 8) & 16) ? -1.f : 1.f;
        #pragma unroll
        for (int nt = 0; nt < 4; nt++) {
            int jb = j0 + warpN + nt * 8 + qc2;
            const float* f0 = &g_F[jb * M2 + ib];
            const float* f1 = &g_F[(jb + 1) * M2 + ib];
            part += s0 * (f0[0] * acc[mt][nt][0] + f1[0] * acc[mt][nt][1]);
            part += s1 * (f0[8] * acc[mt][nt][2] + f1[8] * acc[mt][nt][3]);
        }
    }

    #pragma unroll
    for (int o = 16; o > 0; o >>= 1)
        part += __shfl_xor_sync(0xffffffffu, part, o);
    if (lane == 0) ws[w] = part;
    __syncthreads();
    if (tid == 0) {
        float tot = 0.f;
        #pragma unroll
        for (int k = 0; k < 8; k++) tot += ws[k];
        g_partials[blockIdx.y * gridDim.x + blockIdx.x] = tot;
    }
}

__global__ void reduce_kernel(float* __restrict__ out) {
    __shared__ float s[128];
    int t = threadIdx.x;
    s[t] = g_partials[t];
    __syncthreads();
    for (int st = 64; st > 0; st >>= 1) {
        if (t < st) s[t] += s[t + st];
        __syncthreads();
    }
    if (t == 0) out[0] = s[0];
}

extern "C" void kernel_launch(void* const* d_in, const int* in_sizes, int n_in,
                              void* d_out, int out_size) {
    const float* x = (const float*)d_in[0];      // 1024x1024 row-major
    const float* w = (const float*)d_in[1];      // 30 weights
    cudaFuncSetAttribute(gemm_kernel, cudaFuncAttributeMaxDynamicSharedMemorySize, GEMM_SMEM);
    build_kernel<<<DIM, 512>>>(w);
    split_kernel<<<dim3(32, 64, 2), 256>>>(x);
    gemm_kernel<<<dim3(8, 16), 256, GEMM_SMEM>>>();
    reduce_kernel<<<1, 128>>>((float*)d_out);
}

// round 9
// speedup vs baseline: 2.4428x; 1.2668x over previous
#include <cuda_runtime.h>
#include <cuda_bf16.h>
#include <cstdint>

#define DIM 1024
#define M2  2048   // i dimension: stacked [Re; Im] rows

// Column-of-F storage, i-contiguous (build's natural coalesced layout):
//   g_Fzh[m][i] = z(i) * bf16hi(F[i][m]),  g_Fh[m][i] = bf16hi, g_Fl[m][i] = bf16lo
__device__ __nv_bfloat16 g_Fzh[DIM * M2];
__device__ __nv_bfloat16 g_Fh [DIM * M2];
__device__ __nv_bfloat16 g_Fl [DIM * M2];
__device__ float         g_y  [DIM * DIM];     // y = x + x^T
__device__ float         g_partials[392];
__device__ unsigned      g_cnt;                // zero-init; reset by last CTA

__device__ __forceinline__ uint32_t smem_to_u32(const void* p) {
    uint32_t a;
    asm("{ .reg .u64 t; cvta.to.shared.u64 t, %1; cvt.u32.u64 %0, t; }" : "=r"(a) : "l"(p));
    return a;
}

#define CP_ASYNC16(dst, src) \
    asm volatile("cp.async.ca.shared.global [%0], [%1], 16;" :: "r"(dst), "l"(src) : "memory")
#define CP_COMMIT() asm volatile("cp.async.commit_group;" ::: "memory")
#define CP_WAIT1()  asm volatile("cp.async.wait_group 1;" ::: "memory")
#define CP_WAIT0()  asm volatile("cp.async.wait_group 0;" ::: "memory")

#define LDSM_X4(r, a) \
    asm volatile("ldmatrix.sync.aligned.m8n8.x4.shared.b16 {%0,%1,%2,%3}, [%4];" \
        : "=r"((r)[0]), "=r"((r)[1]), "=r"((r)[2]), "=r"((r)[3]) : "r"(a))

#define MMA_BF16(d, a, b) \
    asm volatile("mma.sync.aligned.m16n8k16.row.col.f32.bf16.bf16.f32 " \
        "{%0,%1,%2,%3},{%4,%5,%6,%7},{%8,%9},{%0,%1,%2,%3};" \
        : "+f"((d)[0]), "+f"((d)[1]), "+f"((d)[2]), "+f"((d)[3]) \
        : "r"((a)[0]), "r"((a)[1]), "r"((a)[2]), "r"((a)[3]), \
          "r"((b)[0]), "r"((b)[1]))

__device__ __forceinline__ float2 cmul(float2 a, float2 b) {
    return make_float2(a.x * b.x - a.y * b.y, a.x * b.y + a.y * b.x);
}
__device__ __forceinline__ float2 cadd(float2 a, float2 b) {
    return make_float2(a.x + b.x, a.y + b.y);
}

// ---------------------------------------------------------------------------
// Fused build kernel:
//   blocks [0,1024): simulate basis column m, write Fzh/Fh/Fl coalesced.
//   blocks [1024,1280): 64x64 tiles of y = x + x^T.
// ---------------------------------------------------------------------------
__global__ __launch_bounds__(512) void build_kernel(const float* __restrict__ w,
                                                    const float* __restrict__ x) {
    __shared__ float  sr[DIM];
    __shared__ float  si[DIM];
    __shared__ float2 sg[2][10][4];
    __shared__ float  tl[64][65];
    int t = threadIdx.x;

    if (blockIdx.x >= 1024) {
        // ---- y = x + x^T, 64x64 tile ----
        int id = blockIdx.x - 1024;            // 0..255
        int a0 = (id >> 4) * 64, b0 = (id & 15) * 64;
        int tx = t & 63, ty = t >> 6;          // 64 x 8
        #pragma unroll
        for (int r = 0; r < 8; r++)            // tl[c][rr] = x[b0+rr][a0+c]
            tl[tx][ty + 8 * r] = x[(b0 + ty + 8 * r) * DIM + a0 + tx];
        __syncthreads();
        #pragma unroll
        for (int r = 0; r < 8; r++) {
            int a = a0 + ty + 8 * r;
            g_y[a * DIM + b0 + tx] = x[a * DIM + b0 + tx] + tl[ty + 8 * r][tx];
        }
        return;
    }

    int col = blockIdx.x;
    if (t < 20) {
        int s = t / 10, q = t % 10;
        float sign = s ? -1.f : 1.f;
        const float WM = 0.63245553203367586f;  // sqrt(2/5)
        float hx = 0.5f * sign * w[q]      * WM;
        float hy = 0.5f * sign * w[q + 10] * WM;
        float hz = 0.5f * sign * w[q + 20] * WM;
        float cx, sx, cy, sy, cz, sz;
        sincosf(hx, &sx, &cx);
        sincosf(hy, &sy, &cy);
        sincosf(hz, &sz, &cz);
        float2 T00 = make_float2( cy * cx,  sy * sx);
        float2 T01 = make_float2(-sy * cx, -cy * sx);
        float2 T10 = make_float2( sy * cx, -cy * sx);
        float2 T11 = make_float2( cy * cx, -sy * sx);
        float2 e0 = make_float2(cz, -sz);
        float2 e1 = make_float2(cz,  sz);
        sg[s][q][0] = cmul(e0, T00);
        sg[s][q][1] = cmul(e0, T01);
        sg[s][q][2] = cmul(e1, T10);
        sg[s][q][3] = cmul(e1, T11);
    }
    sr[t]       = (t == col)       ? 1.f : 0.f;  si[t]       = 0.f;
    sr[t + 512] = (t + 512 == col) ? 1.f : 0.f;  si[t + 512] = 0.f;
    __syncthreads();

    for (int s = 0; s < 2; s++) {
        for (int q = 0; q < 10; q++) {
            int p = 9 - q;
            float2 g00 = sg[s][q][0], g01 = sg[s][q][1];
            float2 g10 = sg[s][q][2], g11 = sg[s][q][3];
            int lo = ((t >> p) << (p + 1)) | (t & ((1 << p) - 1));
            int hi = lo | (1 << p);
            float2 a0 = make_float2(sr[lo], si[lo]);
            float2 a1 = make_float2(sr[hi], si[hi]);
            float2 n0 = cadd(cmul(g00, a0), cmul(g01, a1));
            float2 n1 = cadd(cmul(g10, a0), cmul(g11, a1));
            sr[lo] = n0.x; si[lo] = n0.y;
            sr[hi] = n1.x; si[hi] = n1.y;
            __syncthreads();
        }
        // CNOT chain q=1..9 as composite permutation gather
        int i0 = t, i1 = t + 512;
        int j0 = i0, j1 = i1;
        #pragma unroll
        for (int q = 9; q >= 1; q--) {
            int pc = 10 - q, pt = 9 - q;
            if ((j0 >> pc) & 1) j0 ^= (1 << pt);
            if ((j1 >> pc) & 1) j1 ^= (1 << pt);
        }
        float2 v0 = make_float2(sr[j0], si[j0]);
        float2 v1 = make_float2(sr[j1], si[j1]);
        __syncthreads();
        sr[i0] = v0.x; si[i0] = v0.y;
        sr[i1] = v1.x; si[i1] = v1.y;
        __syncthreads();
    }

    // Write splits, coalesced along i. i = t, t+512 (Re); 1024+t, 1024+t+512 (Im)
    #pragma unroll
    for (int hseg = 0; hseg < 4; hseg++) {
        int i = (hseg >> 1) * 1024 + (hseg & 1) * 512 + t;
        float v = (hseg >> 1) ? si[(hseg & 1) * 512 + t] : sr[(hseg & 1) * 512 + t];
        __nv_bfloat16 h = __float2bfloat16(v);
        float hf = __bfloat162float(h);
        size_t idx = (size_t)col * M2 + i;
        g_Fh [idx] = h;
        g_Fl [idx] = __float2bfloat16(v - hf);
        g_Fzh[idx] = __float2bfloat16((i & 16) ? -hf : hf);
    }
}

// ---------------------------------------------------------------------------
// Symmetric-trace GEMM + fused epilogue + fused final reduction.
//   bid <  256 : T-tile (kb,jb) full grid,  A=Fzh, B=Fl, weight 1
//   bid >= 256 : S-tile kb<=jb triangle,    A=Fzh, B=Fh, weight 1 (0.5 on diag)
// Tile 64x64, K=2048, BK=64, 128 threads (4 warps, 2x2 of 32x32 warp tiles).
// ---------------------------------------------------------------------------
#define BK    64
#define ROWP  144                 // 128B data + 16B pad (banks 0,4,..,28)
#define OPB   (64 * ROWP)         // 9216
#define STAGE (2 * OPB)           // 18432
#define NST   (M2 / BK)           // 32
#define GEMM_SMEM (2 * STAGE)     // 36864

__device__ __forceinline__ void issue_stage(uint32_t sb, int c, int tid,
                                            const __nv_bfloat16* Ab, int am0,
                                            const __nv_bfloat16* Bb, int bn0) {
    uint32_t st = sb + (uint32_t)(c & 1) * STAGE;
    int i0 = c * BK;
    #pragma unroll
    for (int r = 0; r < 8; r++) {
        int chunk = r * 128 + tid;            // 1024 chunks of 16B
        int op  = chunk >> 9;                 // 0=A, 1=B
        int c2  = chunk & 511;
        int row = c2 >> 3, seg = c2 & 7;
        uint32_t dst = st + op * OPB + row * ROWP + seg * 16;
        const __nv_bfloat16* base = op ? (Bb + (size_t)(bn0 + row) * M2)
                                       : (Ab + (size_t)(am0 + row) * M2);
        CP_ASYNC16(dst, base + i0 + seg * 8);
    }
    CP_COMMIT();
}

__global__ __launch_bounds__(128) void gemm_kernel(float* __restrict__ out) {
    extern __shared__ char smem[];
    __shared__ float ws[4];
    __shared__ int isLast;
    const uint32_t sb = smem_to_u32(smem);
    int tid = threadIdx.x;
    int w = tid >> 5, lane = tid & 31;
    int bid = blockIdx.x;

    int kb, jb;
    const __nv_bfloat16* Bb;
    float wgt;
    if (bid < 256) {                      // T = Fzh^T Fl, full
        kb = bid >> 4; jb = bid & 15;
        Bb = g_Fl; wgt = 1.0f;
    } else {                              // S = Fzh^T Fh, upper triangle
        int u = bid - 256, rem = 16;
        kb = 0;
        while (u >= rem) { u -= rem; kb++; rem--; }
        jb = kb + u;
        Bb = g_Fh; wgt = (kb == jb) ? 0.5f : 1.0f;
    }
    int am0 = kb * 64, bn0 = jb * 64;

    float acc[2][4][4];
    #pragma unroll
    for (int a = 0; a < 2; a++)
        #pragma unroll
        for (int b = 0; b < 4; b++)
            #pragma unroll
            for (int d = 0; d < 4; d++) acc[a][b][d] = 0.f;

    int wm = (w >> 1) * 32, wn = (w & 1) * 32;
    int arow = wm + ((lane >> 3) & 1) * 8 + (lane & 7);
    int akb  = (lane >> 4) * 16;
    int brow = wn + (lane >> 4) * 8 + (lane & 7);
    int bkb  = ((lane >> 3) & 1) * 16;

    issue_stage(sb, 0, tid, g_Fzh, am0, Bb, bn0);

    for (int c = 0; c < NST; c++) {
        if (c + 1 < NST) { issue_stage(sb, c + 1, tid, g_Fzh, am0, Bb, bn0); CP_WAIT1(); }
        else             { CP_WAIT0(); }
        __syncthreads();

        uint32_t st = sb + (uint32_t)(c & 1) * STAGE;
        #pragma unroll
        for (int ks = 0; ks < 4; ks++) {
            uint32_t aa[2][4], bb[4][2];
            #pragma unroll
            for (int mt = 0; mt < 2; mt++)
                LDSM_X4(aa[mt], st + (arow + mt * 16) * ROWP + ks * 32 + akb);
            #pragma unroll
            for (int np = 0; np < 2; np++) {
                uint32_t r4[4];
                LDSM_X4(r4, st + OPB + (brow + np * 16) * ROWP + ks * 32 + bkb);
                bb[np * 2][0] = r4[0]; bb[np * 2][1] = r4[1];
                bb[np * 2 + 1][0] = r4[2]; bb[np * 2 + 1][1] = r4[3];
            }
            #pragma unroll
            for (int mt = 0; mt < 2; mt++)
                #pragma unroll
                for (int nt = 0; nt < 4; nt++)
                    MMA_BF16(acc[mt][nt], aa[mt], bb[nt]);
        }
        __syncthreads();
    }

    // Epilogue: part = wgt * sum C_tile[m][n] * y[kg][jg]
    int qr = lane >> 2, qc2 = (lane & 3) * 2;
    float part = 0.f;
    #pragma unroll
    for (int mt = 0; mt < 2; mt++) {
        int kg = am0 + wm + mt * 16 + qr;
        #pragma unroll
        for (int nt = 0; nt < 4; nt++) {
            int jg = bn0 + wn + nt * 8 + qc2;
            const float* y0 = &g_y[kg * DIM + jg];
            const float* y1 = &g_y[(kg + 8) * DIM + jg];
            part += y0[0] * acc[mt][nt][0] + y0[1] * acc[mt][nt][1]
                  + y1[0] * acc[mt][nt][2] + y1[1] * acc[mt][nt][3];
        }
    }
    part *= wgt;

    #pragma unroll
    for (int o = 16; o > 0; o >>= 1)
        part += __shfl_xor_sync(0xffffffffu, part, o);
    if (lane == 0) ws[w] = part;
    __syncthreads();
    if (tid == 0) {
        g_partials[bid] = ws[0] + ws[1] + ws[2] + ws[3];
        __threadfence();
        unsigned old = atomicAdd(&g_cnt, 1u);
        isLast = (old == 391u) ? 1 : 0;
    }
    __syncthreads();

    if (isLast) {
        float v = 0.f;
        for (int i = tid; i < 392; i += 128) v += __ldcg(&g_partials[i]);
        #pragma unroll
        for (int o = 16; o > 0; o >>= 1)
            v += __shfl_xor_sync(0xffffffffu, v, o);
        if (lane == 0) ws[w] = v;
        __syncthreads();
        if (tid == 0) {
            out[0] = ws[0] + ws[1] + ws[2] + ws[3];
            g_cnt = 0;                     // reset for next graph replay
        }
    }
}

extern "C" void kernel_launch(void* const* d_in, const int* in_sizes, int n_in,
                              void* d_out, int out_size) {
    const float* x = (const float*)d_in[0];      // 1024x1024 row-major
    const float* w = (const float*)d_in[1];      // 30 weights
    build_kernel<<<1280, 512>>>(w, x);           // 1024 circuit cols + 256 y-tiles
    gemm_kernel<<<392, 128, GEMM_SMEM>>>((float*)d_out);
}